// round 15
// baseline (speedup 1.0000x reference)
#include <cuda_runtime.h>

#define NN 100000
#define NE 1600000
#define BN_EPS 1e-5f
#define SCAN_BLK 1024
#define N_SCAN_BLKS ((NN + SCAN_BLK - 1) / SCAN_BLK)   // 98
#define FULL 0xffffffffu
#define NE2 (NE / 2)
#define CNT_BLKS ((NE2 + 255) / 256)                    // 3125
#define PROJ_BLKS ((NN + 255) / 256)                    // 391
#define LAYER_GRID ((NN + 127) / 128)                   // 782

typedef unsigned long long u64;

__device__ __forceinline__ u64 pack2(float x, float y) {
    u64 r; asm("mov.b64 %0, {%1, %2};" : "=l"(r) : "f"(x), "f"(y)); return r;
}
__device__ __forceinline__ void unpack2(u64 v, float& x, float& y) {
    asm("mov.b64 {%0, %1}, %2;" : "=f"(x), "=f"(y) : "l"(v));
}
__device__ __forceinline__ u64 fma2(u64 a, u64 b, u64 c) {
    u64 d; asm("fma.rn.f32x2 %0, %1, %2, %3;" : "=l"(d) : "l"(a), "l"(b), "l"(c));
    return d;
}

// ---------------- scratch (static device memory, no allocs) ----------------
__device__ float g_bufA[NN * 32];     // h double buffer A (proj output)
__device__ float g_bufB[NN * 32];     // h double buffer B
__device__ float g_stats[5 * 64];     // zeroed by combo each replay
__device__ float4 g_pool[64 * 8];     // zeroed by combo each replay
// CSR
__device__ int g_cnt[NN];             // histogram -> cursor -> zeroed by pool
__device__ int g_excl[NN];
__device__ int g_bsum[128];
__device__ int g_boff[128];
__device__ int g_rs[NN + 1];
__device__ int g_col[NE];
__device__ int g_done;                // ticket (scan_ab only); self-resets

__device__ __forceinline__ void red_add_f32x4(float4* addr, float4 v) {
    asm volatile("red.global.add.v4.f32 [%0], {%1, %2, %3, %4};"
                 :: "l"(addr), "f"(v.x), "f"(v.y), "f"(v.z), "f"(v.w)
                 : "memory");
}

// BN coeffs for layer l from accumulated stats (32 lanes compute into smem)
__device__ __forceinline__ void bn_coeffs(int l, const float* bn_g,
                                          const float* bn_b,
                                          float* sa, float* sb, int tid) {
    if (tid < 32) {
        float sum = g_stats[l * 64 + tid];
        float sq  = g_stats[l * 64 + 32 + tid];
        const float invN = 1.f / (float)NN;
        float mu  = sum * invN;
        float var = fmaxf(sq * invN - mu * mu, 0.f);
        float a = bn_g[l * 32 + tid] * rsqrtf(var + BN_EPS);
        sa[tid] = a;
        sb[tid] = bn_b[l * 32 + tid] - mu * a;
    }
}

// ---------------- launch 1: count (int2) + proj (mlp-style) + zero ----------
__global__ __launch_bounds__(256) void combo_kernel(
    const float4* __restrict__ x4, const float* __restrict__ W1a,
    const int2* __restrict__ dsts2) {
    int tid = threadIdx.x;
    if (blockIdx.x < CNT_BLKS) {
        int i = blockIdx.x * 256 + tid;
        if (i < NE2) {
            int2 d = __ldg(&dsts2[i]);
            atomicAdd(&g_cnt[d.x], 1);
            atomicAdd(&g_cnt[d.y], 1);
        }
        if (blockIdx.x == 0) {
            float* p = (float*)g_pool;
            for (int k = tid; k < 64 * 8 * 4; k += 256) p[k] = 0.f;
            for (int k = tid; k < 5 * 64; k += 256) g_stats[k] = 0.f;
        }
        return;
    }
    // proj: 256 nodes per block, thread-per-node FFMA2 GEMM (64 -> 32)
    __shared__ __align__(16) float sW[2048];       // 64x32
    __shared__ __align__(16) float px[256 * 65];   // 256 nodes x 64 (+pad)
    for (int i = tid; i < 2048; i += 256) sW[i] = W1a[i];
    int node0 = (blockIdx.x - CNT_BLKS) * 256;
    for (int idx = tid; idx < 256 * 16; idx += 256) {
        int row = idx >> 4, cc = idx & 15;
        if (node0 + row < NN) {
            float4 v = x4[(size_t)(node0 + row) * 16 + cc];
            float* d = &px[row * 65 + cc * 4];
            d[0] = v.x; d[1] = v.y; d[2] = v.z; d[3] = v.w;
        }
    }
    __syncthreads();
    int node = node0 + tid;
    float o[32];
    if (node < NN) {
        const float* xr = &px[tid * 65];
        u64 t2[16];
        #pragma unroll
        for (int m = 0; m < 16; m++) t2[m] = 0ull;
        #pragma unroll
        for (int j = 0; j < 64; j++) {
            float xv = xr[j];
            u64 xv2 = pack2(xv, xv);
            const u64* w2 = (const u64*)&sW[j * 32];
            #pragma unroll
            for (int m = 0; m < 16; m++) t2[m] = fma2(xv2, w2[m], t2[m]);
        }
        #pragma unroll
        for (int m = 0; m < 16; m++) unpack2(t2[m], o[2*m], o[2*m+1]);
    } else {
        #pragma unroll
        for (int k = 0; k < 32; k++) o[k] = 0.f;
    }
    __syncthreads();
    {
        float* xr = &px[tid * 65];
        #pragma unroll
        for (int k = 0; k < 32; k++) xr[k] = o[k];
    }
    __syncthreads();
    for (int idx = tid; idx < 256 * 8; idx += 256) {
        int row = idx >> 3, cc = idx & 7;
        if (node0 + row < NN) {
            const float* s = &px[row * 65 + cc * 4];
            ((float4*)g_bufA)[(size_t)(node0 + row) * 8 + cc] =
                make_float4(s[0], s[1], s[2], s[3]);
        }
    }
}

// ---------------- launch 2: fused scan (per-block + last-block finalize) ---
__global__ __launch_bounds__(256) void scan_ab_kernel() {
    __shared__ int wsum[8];
    __shared__ int slast;
    __shared__ int s[256];
    int base = blockIdx.x * SCAN_BLK + threadIdx.x * 4;
    int v0 = (base + 0 < NN) ? g_cnt[base + 0] : 0;
    int v1 = (base + 1 < NN) ? g_cnt[base + 1] : 0;
    int v2 = (base + 2 < NN) ? g_cnt[base + 2] : 0;
    int v3 = (base + 3 < NN) ? g_cnt[base + 3] : 0;
    if (base + 0 < NN) g_cnt[base + 0] = 0;
    if (base + 1 < NN) g_cnt[base + 1] = 0;
    if (base + 2 < NN) g_cnt[base + 2] = 0;
    if (base + 3 < NN) g_cnt[base + 3] = 0;
    int tsum = v0 + v1 + v2 + v3;
    int lane = threadIdx.x & 31, wid = threadIdx.x >> 5;
    int incl = tsum;
    #pragma unroll
    for (int off = 1; off < 32; off <<= 1) {
        int n = __shfl_up_sync(FULL, incl, off);
        if (lane >= off) incl += n;
    }
    if (lane == 31) wsum[wid] = incl;
    __syncthreads();
    if (wid == 0 && lane < 8) {
        int w = wsum[lane];
        #pragma unroll
        for (int off = 1; off < 8; off <<= 1) {
            int n = __shfl_up_sync(0xffu, w, off);
            if (lane >= off) w += n;
        }
        wsum[lane] = w;
    }
    __syncthreads();
    int off = (wid > 0 ? wsum[wid - 1] : 0) + incl - tsum;
    if (base + 0 < NN) g_excl[base + 0] = off;
    if (base + 1 < NN) g_excl[base + 1] = off + v0;
    if (base + 2 < NN) g_excl[base + 2] = off + v0 + v1;
    if (base + 3 < NN) g_excl[base + 3] = off + v0 + v1 + v2;
    if (threadIdx.x == 0) g_bsum[blockIdx.x] = wsum[7];

    __threadfence();
    if (threadIdx.x == 0) slast = atomicAdd(&g_done, 1);
    __syncthreads();
    if (slast == N_SCAN_BLKS - 1) {
        int t = threadIdx.x;
        int val = (t < N_SCAN_BLKS) ? g_bsum[t] : 0;
        s[t] = val;
        __syncthreads();
        #pragma unroll
        for (int o = 1; o < 256; o <<= 1) {
            int v = (t >= o) ? s[t - o] : 0;
            __syncthreads();
            s[t] += v;
            __syncthreads();
        }
        if (t < N_SCAN_BLKS) g_boff[t] = s[t] - val;
        if (t == 0) g_done = 0;
    }
}

// ---------------- launch 3: rs write + CSR fill (2 edges/thread) ------------
__global__ __launch_bounds__(256) void fill_kernel(const int2* __restrict__ srcs2,
                                                   const int2* __restrict__ dsts2) {
    int idx = blockIdx.x * 256 + threadIdx.x;
    if (idx < NN) g_rs[idx] = g_excl[idx] + g_boff[idx >> 10];
    if (idx == 0) g_rs[NN] = NE;
    if (idx >= NE2) return;
    int2 d = __ldg(&dsts2[idx]);
    int2 sv = __ldg(&srcs2[idx]);
    int rs0 = g_excl[d.x] + g_boff[d.x >> 10];
    int p0 = rs0 + atomicAdd(&g_cnt[d.x], 1);
    g_col[p0] = sv.x;
    int rs1 = g_excl[d.y] + g_boff[d.y >> 10];
    int p1 = rs1 + atomicAdd(&g_cnt[d.y], 1);
    g_col[p1] = sv.y;
}

// ---------------- fused layer: gather (smem) + MLP (2 thr/node) + stats -----
// 256 threads, 128 nodes/block. Gather keeps R14's exact pattern; MLP keeps
// FFMA2 register GEMM split 2-way per node with smem handoff.
template<bool FIRST>
__global__ __launch_bounds__(256, 7) void layer_kernel(
    const float* __restrict__ Wa, const float* __restrict__ Ba,
    const float* __restrict__ Wb, const float* __restrict__ Bb, int layer,
    const float* __restrict__ bn_g, const float* __restrict__ bn_b) {
    __shared__ __align__(16) float sW1[1024];
    __shared__ __align__(16) float sW2[1024];
    __shared__ float sBa[32], sBb[32], sa[32], sb[32];
    __shared__ __align__(16) float sx[128 * 33];
    __shared__ float sdeg[128];
    __shared__ float sred[256];
    int tid = threadIdx.x;
    for (int i = tid; i < 1024; i += 256) {
        if (!FIRST) sW1[i] = Wa[i];
        sW2[i] = Wb[i];
    }
    if (tid < 32) { sBa[tid] = Ba[tid]; sBb[tid] = Bb[tid]; }
    if (!FIRST) bn_coeffs(layer - 1, bn_g, bn_b, sa, sb, tid);

    const float4* fin = (const float4*)((layer & 1) ? g_bufB : g_bufA);
    float4*       fout = (float4*)((layer & 1) ? g_bufA : g_bufB);

    int node0 = blockIdx.x * 128;
    int c = tid & 7;

    // ---- gather phase: 4 rounds x 32 nodes (8 lanes/node, R14 pattern) ----
    #pragma unroll 1
    for (int r = 0; r < 4; r++) {
        int ln = r * 32 + (tid >> 3);
        int node = node0 + ln;
        float4 a0 = make_float4(0.f, 0.f, 0.f, 0.f);
        float4 a1 = make_float4(0.f, 0.f, 0.f, 0.f);
        if (node < NN) {
            int e0 = g_rs[node], e1 = g_rs[node + 1];
            if (c == 0) sdeg[ln] = (float)(e1 - e0 + 1);
            a0 = __ldg(&fin[(size_t)node * 8 + c]);
            int e = e0;
            for (; e + 4 <= e1; e += 4) {
                int i0 = __ldg(&g_col[e + 0]);
                int i1 = __ldg(&g_col[e + 1]);
                int i2 = __ldg(&g_col[e + 2]);
                int i3 = __ldg(&g_col[e + 3]);
                float4 v0 = __ldg(&fin[(size_t)i0 * 8 + c]);
                float4 v1 = __ldg(&fin[(size_t)i1 * 8 + c]);
                float4 v2 = __ldg(&fin[(size_t)i2 * 8 + c]);
                float4 v3 = __ldg(&fin[(size_t)i3 * 8 + c]);
                a0.x += v0.x + v2.x; a0.y += v0.y + v2.y;
                a0.z += v0.z + v2.z; a0.w += v0.w + v2.w;
                a1.x += v1.x + v3.x; a1.y += v1.y + v3.y;
                a1.z += v1.z + v3.z; a1.w += v1.w + v3.w;
            }
            for (; e < e1; e++) {
                int s = __ldg(&g_col[e]);
                float4 v = __ldg(&fin[(size_t)s * 8 + c]);
                a0.x += v.x; a0.y += v.y; a0.z += v.z; a0.w += v.w;
            }
        } else if (c == 0) sdeg[ln] = 0.f;
        float* d = &sx[ln * 33 + c * 4];
        d[0] = a0.x + a1.x; d[1] = a0.y + a1.y;
        d[2] = a0.z + a1.z; d[3] = a0.w + a1.w;
    }
    __syncthreads();

    // ---- MLP phase: 2 threads per node, 16 outputs each ----
    int ln = tid >> 1;
    int hh = tid & 1;
    int node = node0 + ln;
    bool active = node < NN;
    float t[16];
    if (active) {
        const float* xr = &sx[ln * 33];
        if (FIRST) {
            #pragma unroll
            for (int k = 0; k < 16; k++)
                t[k] = fmaxf(xr[hh * 16 + k] + sBa[hh * 16 + k], 0.f);
        } else {
            float cnt = sdeg[ln];
            u64 t2[8];
            #pragma unroll
            for (int m = 0; m < 8; m++)
                t2[m] = pack2(sBa[hh * 16 + 2 * m], sBa[hh * 16 + 2 * m + 1]);
            #pragma unroll
            for (int j = 0; j < 32; j++) {
                float xv = fmaf(sa[j], xr[j], cnt * sb[j]);
                u64 xv2 = pack2(xv, xv);
                const u64* w2 = (const u64*)&sW1[j * 32 + hh * 16];
                #pragma unroll
                for (int m = 0; m < 8; m++) t2[m] = fma2(xv2, w2[m], t2[m]);
            }
            #pragma unroll
            for (int m = 0; m < 8; m++) {
                unpack2(t2[m], t[2 * m], t[2 * m + 1]);
                t[2 * m]     = fmaxf(t[2 * m], 0.f);
                t[2 * m + 1] = fmaxf(t[2 * m + 1], 0.f);
            }
        }
    } else {
        #pragma unroll
        for (int k = 0; k < 16; k++) t[k] = 0.f;
    }
    __syncthreads();   // all agg reads done
    {
        float* d = &sx[ln * 33 + hh * 16];
        #pragma unroll
        for (int k = 0; k < 16; k++) d[k] = t[k];
    }
    __syncthreads();
    float o[16];
    if (active) {
        const float* tr = &sx[ln * 33];
        u64 o2[8];
        #pragma unroll
        for (int m = 0; m < 8; m++)
            o2[m] = pack2(sBb[hh * 16 + 2 * m], sBb[hh * 16 + 2 * m + 1]);
        #pragma unroll
        for (int j = 0; j < 32; j++) {
            float tj = tr[j];
            u64 tj2 = pack2(tj, tj);
            const u64* w2 = (const u64*)&sW2[j * 32 + hh * 16];
            #pragma unroll
            for (int m = 0; m < 8; m++) o2[m] = fma2(tj2, w2[m], o2[m]);
        }
        #pragma unroll
        for (int m = 0; m < 8; m++) {
            unpack2(o2[m], o[2 * m], o[2 * m + 1]);
            o[2 * m]     = fmaxf(o[2 * m], 0.f);
            o[2 * m + 1] = fmaxf(o[2 * m + 1], 0.f);
        }
    } else {
        #pragma unroll
        for (int k = 0; k < 16; k++) o[k] = 0.f;
    }
    __syncthreads();   // all t reads done
    {
        float* d = &sx[ln * 33 + hh * 16];
        #pragma unroll
        for (int k = 0; k < 16; k++) d[k] = o[k];
    }
    __syncthreads();
    // coalesced store of h (128 rows x 8 float4)
    for (int idx = tid; idx < 128 * 8; idx += 256) {
        int row = idx >> 3, cc = idx & 7;
        if (node0 + row < NN) {
            const float* s = &sx[row * 33 + cc * 4];
            fout[(size_t)(node0 + row) * 8 + cc] =
                make_float4(s[0], s[1], s[2], s[3]);
        }
    }
    // fused stats: 8 parts x 16 rows, then 32-thread reduce
    {
        int col = tid & 31;
        int part = tid >> 5;    // 0..7
        float s = 0.f, q = 0.f;
        for (int r = part * 16; r < part * 16 + 16; r++) {
            float v = sx[r * 33 + col];
            s += v; q += v * v;
        }
        sred[tid] = s;
        __syncthreads();
        float stot = 0.f;
        if (tid < 32) {
            #pragma unroll
            for (int p = 0; p < 8; p++) stot += sred[tid + 32 * p];
        }
        __syncthreads();
        sred[tid] = q;
        __syncthreads();
        if (tid < 32) {
            float qtot = 0.f;
            #pragma unroll
            for (int p = 0; p < 8; p++) qtot += sred[tid + 32 * p];
            atomicAdd(&g_stats[layer * 64 + tid], stot);
            atomicAdd(&g_stats[layer * 64 + 32 + tid], qtot);
        }
    }
}

// ---------------- pool: BN (per block from stats[4]) + g_cnt reset ----------
// final h lives in g_bufB (layer 4 writes B)
__global__ __launch_bounds__(256) void pool_kernel(
    const int* __restrict__ batch,
    const float* __restrict__ bn_g, const float* __restrict__ bn_b) {
    __shared__ float sa[32], sb[32];
    int tid0 = threadIdx.x;
    bn_coeffs(4, bn_g, bn_b, sa, sb, tid0);
    __syncthreads();
    int tid = blockIdx.x * 256 + tid0;
    if (tid >= NN * 8) return;
    int n = tid >> 3, c = tid & 7;
    if (c == 0) g_cnt[n] = 0;          // reset histogram for next replay
    float4 v = ((const float4*)g_bufB)[(size_t)n * 8 + c];
    int col = c * 4;
    v.x = fmaf(v.x, sa[col + 0], sb[col + 0]);
    v.y = fmaf(v.y, sa[col + 1], sb[col + 1]);
    v.z = fmaf(v.z, sa[col + 2], sb[col + 2]);
    v.w = fmaf(v.w, sa[col + 3], sb[col + 3]);
    int g = batch[n];
    red_add_f32x4(&g_pool[g * 8 + c], v);
}

// ---------------- head ------------------------------------------------------
__global__ void head_kernel(const float* __restrict__ fc1w, const float* __restrict__ fc1b,
                            const float* __restrict__ fc2w, const float* __restrict__ fc2b,
                            float* __restrict__ out) {
    int g = threadIdx.x;
    if (g >= 64) return;
    float in[32];
    #pragma unroll
    for (int j = 0; j < 8; j++) {
        float4 v = g_pool[g * 8 + j];
        in[4*j+0] = v.x; in[4*j+1] = v.y; in[4*j+2] = v.z; in[4*j+3] = v.w;
    }
    float t[32];
    #pragma unroll
    for (int k = 0; k < 32; k++) t[k] = fc1b[k];
    #pragma unroll
    for (int j = 0; j < 32; j++) {
        float xv = in[j];
        #pragma unroll
        for (int k = 0; k < 32; k++) t[k] = fmaf(xv, fc1w[j * 32 + k], t[k]);
    }
    #pragma unroll
    for (int k = 0; k < 32; k++) t[k] = fmaxf(t[k], 0.f);
    float o[10];
    #pragma unroll
    for (int c = 0; c < 10; c++) o[c] = fc2b[c];
    #pragma unroll
    for (int j = 0; j < 32; j++) {
        float xv = t[j];
        #pragma unroll
        for (int c = 0; c < 10; c++) o[c] = fmaf(xv, fc2w[j * 10 + c], o[c]);
    }
    #pragma unroll
    for (int c = 0; c < 10; c++) out[g * 10 + c] = o[c];
}

// ---------------- launch ----------------------------------------------------
extern "C" void kernel_launch(void* const* d_in, const int* in_sizes, int n_in,
                              void* d_out, int out_size) {
    const float* x     = (const float*)d_in[0];
    const int*   ei    = (const int*)d_in[1];
    const int*   batch = (const int*)d_in[2];
    const float* w1a = (const float*)d_in[3];
    const float* b1a = (const float*)d_in[4];
    const float* w1b = (const float*)d_in[5];
    const float* b1b = (const float*)d_in[6];
    const float* Wa  = (const float*)d_in[7];
    const float* Ba  = (const float*)d_in[8];
    const float* Wb  = (const float*)d_in[9];
    const float* Bb  = (const float*)d_in[10];
    const float* bng = (const float*)d_in[11];
    const float* bnb = (const float*)d_in[12];
    const float* fc1w = (const float*)d_in[13];
    const float* fc1b = (const float*)d_in[14];
    const float* fc2w = (const float*)d_in[15];
    const float* fc2b = (const float*)d_in[16];
    float* out = (float*)d_out;

    const int2* srcs2 = (const int2*)ei;
    const int2* dsts2 = (const int2*)(ei + NE);

    const int POOL_GRID = (NN * 8 + 255) / 256;

    // launches 1-3: CSR build + proj
    combo_kernel<<<CNT_BLKS + PROJ_BLKS, 256>>>((const float4*)x, w1a, dsts2);
    scan_ab_kernel<<<N_SCAN_BLKS, 256>>>();
    fill_kernel<<<CNT_BLKS, 256>>>(srcs2, dsts2);

    // fused layers 1-5 (launch 4 = layer 1 -> profiled)
    layer_kernel<true><<<LAYER_GRID, 256>>>(nullptr, b1a, w1b, b1b, 0, bng, bnb);
    for (int i = 0; i < 4; i++) {
        layer_kernel<false><<<LAYER_GRID, 256>>>(Wa + i * 1024, Ba + i * 32,
                                                 Wb + i * 1024, Bb + i * 32,
                                                 i + 1, bng, bnb);
    }

    pool_kernel<<<POOL_GRID, 256>>>(batch, bng, bnb);
    head_kernel<<<1, 64>>>(fc1w, fc1b, fc2w, fc2b, out);
}

// round 16
// speedup vs baseline: 1.2502x; 1.2502x over previous
#include <cuda_runtime.h>

#define NN 100000
#define NE 1600000
#define BN_EPS 1e-5f
#define SCAN_BLK 1024
#define N_SCAN_BLKS ((NN + SCAN_BLK - 1) / SCAN_BLK)   // 98
#define FULL 0xffffffffu
#define NE4 (NE / 4)
#define CNT_BLKS ((NE4 + 255) / 256)                    // 1563
#define PROJ_BLKS ((NN + 255) / 256)                    // 391
#define MLP_GRID ((NN + 127) / 128)                     // 782

typedef unsigned long long u64;

__device__ __forceinline__ u64 pack2(float x, float y) {
    u64 r; asm("mov.b64 %0, {%1, %2};" : "=l"(r) : "f"(x), "f"(y)); return r;
}
__device__ __forceinline__ void unpack2(u64 v, float& x, float& y) {
    asm("mov.b64 {%0, %1}, %2;" : "=f"(x), "=f"(y) : "l"(v));
}
__device__ __forceinline__ u64 fma2(u64 a, u64 b, u64 c) {
    u64 d; asm("fma.rn.f32x2 %0, %1, %2, %3;" : "=l"(d) : "l"(a), "l"(b), "l"(c));
    return d;
}

// ---------------- scratch (static device memory, no allocs) ----------------
__device__ float g_bufA[NN * 32];     // node features h (fp32)
__device__ float g_agg[NN * 32];      // gathered sums
__device__ float g_stats[5 * 64];     // zeroed by combo each replay
__device__ float4 g_pool[64 * 8];     // zeroed by combo each replay
// CSR
__device__ int g_cnt[NN];             // histogram -> cursor -> zeroed by pool
__device__ int g_excl[NN];
__device__ int g_bsum[128];
__device__ int g_boff[128];
__device__ int g_rs[NN + 1];
__device__ int g_col[NE];
__device__ int g_done;                // ticket (scan_ab only); self-resets

__device__ __forceinline__ void red_add_f32x4(float4* addr, float4 v) {
    asm volatile("red.global.add.v4.f32 [%0], {%1, %2, %3, %4};"
                 :: "l"(addr), "f"(v.x), "f"(v.y), "f"(v.z), "f"(v.w)
                 : "memory");
}

// BN coeffs for layer l from accumulated stats (32 lanes compute into smem)
__device__ __forceinline__ void bn_coeffs(int l, const float* bn_g,
                                          const float* bn_b,
                                          float* sa, float* sb, int tid) {
    if (tid < 32) {
        float sum = g_stats[l * 64 + tid];
        float sq  = g_stats[l * 64 + 32 + tid];
        const float invN = 1.f / (float)NN;
        float mu  = sum * invN;
        float var = fmaxf(sq * invN - mu * mu, 0.f);
        float a = bn_g[l * 32 + tid] * rsqrtf(var + BN_EPS);
        sa[tid] = a;
        sb[tid] = bn_b[l * 32 + tid] - mu * a;
    }
}

// ---------------- launch 1: count (int4) + proj (mlp-style) + zero ----------
__global__ __launch_bounds__(256) void combo_kernel(
    const float4* __restrict__ x4, const float* __restrict__ W1a,
    const int4* __restrict__ dsts4) {
    int tid = threadIdx.x;
    if (blockIdx.x < CNT_BLKS) {
        int i = blockIdx.x * 256 + tid;
        if (i < NE4) {
            int4 d = __ldg(&dsts4[i]);
            atomicAdd(&g_cnt[d.x], 1);
            atomicAdd(&g_cnt[d.y], 1);
            atomicAdd(&g_cnt[d.z], 1);
            atomicAdd(&g_cnt[d.w], 1);
        }
        if (blockIdx.x == 0) {
            float* p = (float*)g_pool;
            for (int k = tid; k < 64 * 8 * 4; k += 256) p[k] = 0.f;
            for (int k = tid; k < 5 * 64; k += 256) g_stats[k] = 0.f;
        }
        return;
    }
    // proj: 256 nodes per block, thread-per-node FFMA2 GEMM (64 -> 32)
    __shared__ __align__(16) float sW[2048];       // 64x32
    __shared__ __align__(16) float px[256 * 65];   // 256 nodes x 64 (+pad)
    for (int i = tid; i < 2048; i += 256) sW[i] = W1a[i];
    int node0 = (blockIdx.x - CNT_BLKS) * 256;
    for (int idx = tid; idx < 256 * 16; idx += 256) {
        int row = idx >> 4, cc = idx & 15;
        if (node0 + row < NN) {
            float4 v = x4[(size_t)(node0 + row) * 16 + cc];
            float* d = &px[row * 65 + cc * 4];
            d[0] = v.x; d[1] = v.y; d[2] = v.z; d[3] = v.w;
        }
    }
    __syncthreads();
    int node = node0 + tid;
    float o[32];
    if (node < NN) {
        const float* xr = &px[tid * 65];
        u64 t2[16];
        #pragma unroll
        for (int m = 0; m < 16; m++) t2[m] = 0ull;
        #pragma unroll
        for (int j = 0; j < 64; j++) {
            float xv = xr[j];
            u64 xv2 = pack2(xv, xv);
            const u64* w2 = (const u64*)&sW[j * 32];
            #pragma unroll
            for (int m = 0; m < 16; m++) t2[m] = fma2(xv2, w2[m], t2[m]);
        }
        #pragma unroll
        for (int m = 0; m < 16; m++) unpack2(t2[m], o[2*m], o[2*m+1]);
    } else {
        #pragma unroll
        for (int k = 0; k < 32; k++) o[k] = 0.f;
    }
    __syncthreads();
    {
        float* xr = &px[tid * 65];
        #pragma unroll
        for (int k = 0; k < 32; k++) xr[k] = o[k];
    }
    __syncthreads();
    for (int idx = tid; idx < 256 * 8; idx += 256) {
        int row = idx >> 3, cc = idx & 7;
        if (node0 + row < NN) {
            const float* s = &px[row * 65 + cc * 4];
            ((float4*)g_bufA)[(size_t)(node0 + row) * 8 + cc] =
                make_float4(s[0], s[1], s[2], s[3]);
        }
    }
}

// ---------------- launch 2: fused scan (per-block + last-block finalize) ---
__global__ __launch_bounds__(256) void scan_ab_kernel() {
    __shared__ int wsum[8];
    __shared__ int slast;
    __shared__ int s[256];
    int base = blockIdx.x * SCAN_BLK + threadIdx.x * 4;
    int v0 = (base + 0 < NN) ? g_cnt[base + 0] : 0;
    int v1 = (base + 1 < NN) ? g_cnt[base + 1] : 0;
    int v2 = (base + 2 < NN) ? g_cnt[base + 2] : 0;
    int v3 = (base + 3 < NN) ? g_cnt[base + 3] : 0;
    if (base + 0 < NN) g_cnt[base + 0] = 0;    // reset -> fill cursor
    if (base + 1 < NN) g_cnt[base + 1] = 0;
    if (base + 2 < NN) g_cnt[base + 2] = 0;
    if (base + 3 < NN) g_cnt[base + 3] = 0;
    int tsum = v0 + v1 + v2 + v3;
    int lane = threadIdx.x & 31, wid = threadIdx.x >> 5;
    int incl = tsum;
    #pragma unroll
    for (int off = 1; off < 32; off <<= 1) {
        int n = __shfl_up_sync(FULL, incl, off);
        if (lane >= off) incl += n;
    }
    if (lane == 31) wsum[wid] = incl;
    __syncthreads();
    if (wid == 0 && lane < 8) {
        int w = wsum[lane];
        #pragma unroll
        for (int off = 1; off < 8; off <<= 1) {
            int n = __shfl_up_sync(0xffu, w, off);
            if (lane >= off) w += n;
        }
        wsum[lane] = w;
    }
    __syncthreads();
    int off = (wid > 0 ? wsum[wid - 1] : 0) + incl - tsum;
    if (base + 0 < NN) g_excl[base + 0] = off;
    if (base + 1 < NN) g_excl[base + 1] = off + v0;
    if (base + 2 < NN) g_excl[base + 2] = off + v0 + v1;
    if (base + 3 < NN) g_excl[base + 3] = off + v0 + v1 + v2;
    if (threadIdx.x == 0) g_bsum[blockIdx.x] = wsum[7];

    __threadfence();
    if (threadIdx.x == 0) slast = atomicAdd(&g_done, 1);
    __syncthreads();
    if (slast == N_SCAN_BLKS - 1) {
        int t = threadIdx.x;
        int val = (t < N_SCAN_BLKS) ? g_bsum[t] : 0;
        s[t] = val;
        __syncthreads();
        #pragma unroll
        for (int o = 1; o < 256; o <<= 1) {
            int v = (t >= o) ? s[t - o] : 0;
            __syncthreads();
            s[t] += v;
            __syncthreads();
        }
        if (t < N_SCAN_BLKS) g_boff[t] = s[t] - val;
        if (t == 0) g_done = 0;
    }
}

// ---------------- launch 3: rs write + CSR fill (4 edges/thread) ------------
__global__ __launch_bounds__(256) void fill_kernel(const int4* __restrict__ srcs4,
                                                   const int4* __restrict__ dsts4) {
    int idx = blockIdx.x * 256 + threadIdx.x;
    if (idx < NN) g_rs[idx] = g_excl[idx] + g_boff[idx >> 10];
    if (idx == 0) g_rs[NN] = NE;
    if (idx >= NE4) return;
    int4 d = __ldg(&dsts4[idx]);
    int4 sv = __ldg(&srcs4[idx]);
    int p0 = g_excl[d.x] + g_boff[d.x >> 10] + atomicAdd(&g_cnt[d.x], 1);
    g_col[p0] = sv.x;
    int p1 = g_excl[d.y] + g_boff[d.y >> 10] + atomicAdd(&g_cnt[d.y], 1);
    g_col[p1] = sv.y;
    int p2 = g_excl[d.z] + g_boff[d.z >> 10] + atomicAdd(&g_cnt[d.z], 1);
    g_col[p2] = sv.z;
    int p3 = g_excl[d.w] + g_boff[d.w >> 10] + atomicAdd(&g_cnt[d.w], 1);
    g_col[p3] = sv.w;
}

// ---------------- gather: 8 lanes/node, 4 loads in flight, 2 accumulators ---
// __launch_bounds__(256, 8) caps regs at 32 -> 2048 threads/SM
__global__ __launch_bounds__(256, 8) void gather_kernel() {
    int tid = blockIdx.x * 256 + threadIdx.x;
    int node = tid >> 3;
    int c = tid & 7;
    if (node >= NN) return;
    const float4* fin = (const float4*)g_bufA;
    int e0 = g_rs[node], e1 = g_rs[node + 1];
    float4 a0 = __ldg(&fin[(size_t)node * 8 + c]);
    float4 a1 = make_float4(0.f, 0.f, 0.f, 0.f);
    int e = e0;
    for (; e + 4 <= e1; e += 4) {
        int i0 = __ldg(&g_col[e + 0]);
        int i1 = __ldg(&g_col[e + 1]);
        int i2 = __ldg(&g_col[e + 2]);
        int i3 = __ldg(&g_col[e + 3]);
        float4 v0 = __ldg(&fin[(size_t)i0 * 8 + c]);
        float4 v1 = __ldg(&fin[(size_t)i1 * 8 + c]);
        float4 v2 = __ldg(&fin[(size_t)i2 * 8 + c]);
        float4 v3 = __ldg(&fin[(size_t)i3 * 8 + c]);
        a0.x += v0.x + v2.x; a0.y += v0.y + v2.y;
        a0.z += v0.z + v2.z; a0.w += v0.w + v2.w;
        a1.x += v1.x + v3.x; a1.y += v1.y + v3.y;
        a1.z += v1.z + v3.z; a1.w += v1.w + v3.w;
    }
    for (; e < e1; e++) {
        int s = __ldg(&g_col[e]);
        float4 v = __ldg(&fin[(size_t)s * 8 + c]);
        a0.x += v.x; a0.y += v.y; a0.z += v.z; a0.w += v.w;
    }
    float4 r;
    r.x = a0.x + a1.x;
    r.y = a0.y + a1.y;
    r.z = a0.z + a1.z;
    r.w = a0.w + a1.w;
    ((float4*)g_agg)[(size_t)node * 8 + c] = r;
}

// ---------------- MLP (FFMA2) + fused stats; per-block BN of prev layer -----
template<bool FIRST>
__global__ __launch_bounds__(128) void mlp_kernel(
    const float* __restrict__ Wa, const float* __restrict__ Ba,
    const float* __restrict__ Wb, const float* __restrict__ Bb, int layer,
    const float* __restrict__ bn_g, const float* __restrict__ bn_b) {
    __shared__ __align__(16) float sW1[1024];
    __shared__ __align__(16) float sW2[1024];
    __shared__ float sBa[32], sBb[32], sa[32], sb[32];
    __shared__ __align__(16) float sx[128 * 33];
    __shared__ float sred[256];
    int tid = threadIdx.x;
    for (int i = tid; i < 1024; i += 128) {
        if (!FIRST) sW1[i] = Wa[i];
        sW2[i] = Wb[i];
    }
    if (tid < 32) { sBa[tid] = Ba[tid]; sBb[tid] = Bb[tid]; }
    if (!FIRST) bn_coeffs(layer - 1, bn_g, bn_b, sa, sb, tid);

    int node0 = blockIdx.x * 128;
    for (int idx = tid; idx < 128 * 8; idx += 128) {
        int row = idx >> 3, cc = idx & 7;
        if (node0 + row < NN) {
            float4 v = ((const float4*)g_agg)[(size_t)(node0 + row) * 8 + cc];
            float* d = &sx[row * 33 + cc * 4];
            d[0] = v.x; d[1] = v.y; d[2] = v.z; d[3] = v.w;
        }
    }
    __syncthreads();

    int node = node0 + tid;
    bool active = node < NN;
    float o[32];
    if (active) {
        const float* xr = &sx[tid * 33];
        float t[32];
        if (FIRST) {
            #pragma unroll
            for (int k = 0; k < 32; k++) t[k] = fmaxf(xr[k] + sBa[k], 0.f);
        } else {
            float cnt = (float)(g_rs[node + 1] - g_rs[node] + 1);
            u64 t2[16];
            #pragma unroll
            for (int m = 0; m < 16; m++) t2[m] = pack2(sBa[2*m], sBa[2*m+1]);
            #pragma unroll
            for (int j = 0; j < 32; j++) {
                float xv = fmaf(sa[j], xr[j], cnt * sb[j]);
                u64 xv2 = pack2(xv, xv);
                const u64* w2 = (const u64*)&sW1[j * 32];
                #pragma unroll
                for (int m = 0; m < 16; m++) t2[m] = fma2(xv2, w2[m], t2[m]);
            }
            #pragma unroll
            for (int m = 0; m < 16; m++) unpack2(t2[m], t[2*m], t[2*m+1]);
            #pragma unroll
            for (int k = 0; k < 32; k++) t[k] = fmaxf(t[k], 0.f);
        }
        u64 o2[16];
        #pragma unroll
        for (int m = 0; m < 16; m++) o2[m] = pack2(sBb[2*m], sBb[2*m+1]);
        #pragma unroll
        for (int j = 0; j < 32; j++) {
            u64 tj2 = pack2(t[j], t[j]);
            const u64* w2 = (const u64*)&sW2[j * 32];
            #pragma unroll
            for (int m = 0; m < 16; m++) o2[m] = fma2(tj2, w2[m], o2[m]);
        }
        #pragma unroll
        for (int m = 0; m < 16; m++) unpack2(o2[m], o[2*m], o[2*m+1]);
        #pragma unroll
        for (int k = 0; k < 32; k++) o[k] = fmaxf(o[k], 0.f);
    } else {
        #pragma unroll
        for (int k = 0; k < 32; k++) o[k] = 0.f;
    }
    __syncthreads();
    {
        float* xr = &sx[tid * 33];
        #pragma unroll
        for (int k = 0; k < 32; k++) xr[k] = o[k];
    }
    __syncthreads();
    for (int idx = tid; idx < 128 * 8; idx += 128) {
        int row = idx >> 3, cc = idx & 7;
        if (node0 + row < NN) {
            const float* s = &sx[row * 33 + cc * 4];
            ((float4*)g_bufA)[(size_t)(node0 + row) * 8 + cc] =
                make_float4(s[0], s[1], s[2], s[3]);
        }
    }
    // fused stats: 4 row-partials per column, then 64-thread reduce
    {
        int col = tid & 31;
        int part = tid >> 5;
        float s = 0.f, q = 0.f;
        for (int r = part * 32; r < part * 32 + 32; r++) {
            float v = sx[r * 33 + col];
            s += v; q += v * v;
        }
        sred[tid] = s;
        __syncthreads();
        float stot = 0.f;
        if (tid < 32) stot = sred[tid] + sred[32+tid] + sred[64+tid] + sred[96+tid];
        __syncthreads();
        sred[tid] = q;
        __syncthreads();
        if (tid < 32) {
            float qtot = sred[tid] + sred[32+tid] + sred[64+tid] + sred[96+tid];
            atomicAdd(&g_stats[layer * 64 + tid], stot);
            atomicAdd(&g_stats[layer * 64 + 32 + tid], qtot);
        }
    }
}

// ---------------- pool: BN (per block from stats[4]) + g_cnt reset ----------
__global__ __launch_bounds__(256) void pool_kernel(
    const int* __restrict__ batch,
    const float* __restrict__ bn_g, const float* __restrict__ bn_b) {
    __shared__ float sa[32], sb[32];
    int tid0 = threadIdx.x;
    bn_coeffs(4, bn_g, bn_b, sa, sb, tid0);
    __syncthreads();
    int tid = blockIdx.x * 256 + tid0;
    if (tid >= NN * 8) return;
    int n = tid >> 3, c = tid & 7;
    if (c == 0) g_cnt[n] = 0;          // reset histogram for next replay
    float4 v = ((const float4*)g_bufA)[(size_t)n * 8 + c];
    int col = c * 4;
    v.x = fmaf(v.x, sa[col + 0], sb[col + 0]);
    v.y = fmaf(v.y, sa[col + 1], sb[col + 1]);
    v.z = fmaf(v.z, sa[col + 2], sb[col + 2]);
    v.w = fmaf(v.w, sa[col + 3], sb[col + 3]);
    int g = batch[n];
    red_add_f32x4(&g_pool[g * 8 + c], v);
}

// ---------------- head ------------------------------------------------------
__global__ void head_kernel(const float* __restrict__ fc1w, const float* __restrict__ fc1b,
                            const float* __restrict__ fc2w, const float* __restrict__ fc2b,
                            float* __restrict__ out) {
    int g = threadIdx.x;
    if (g >= 64) return;
    float in[32];
    #pragma unroll
    for (int j = 0; j < 8; j++) {
        float4 v = g_pool[g * 8 + j];
        in[4*j+0] = v.x; in[4*j+1] = v.y; in[4*j+2] = v.z; in[4*j+3] = v.w;
    }
    float t[32];
    #pragma unroll
    for (int k = 0; k < 32; k++) t[k] = fc1b[k];
    #pragma unroll
    for (int j = 0; j < 32; j++) {
        float xv = in[j];
        #pragma unroll
        for (int k = 0; k < 32; k++) t[k] = fmaf(xv, fc1w[j * 32 + k], t[k]);
    }
    #pragma unroll
    for (int k = 0; k < 32; k++) t[k] = fmaxf(t[k], 0.f);
    float o[10];
    #pragma unroll
    for (int c = 0; c < 10; c++) o[c] = fc2b[c];
    #pragma unroll
    for (int j = 0; j < 32; j++) {
        float xv = t[j];
        #pragma unroll
        for (int c = 0; c < 10; c++) o[c] = fmaf(xv, fc2w[j * 10 + c], o[c]);
    }
    #pragma unroll
    for (int c = 0; c < 10; c++) out[g * 10 + c] = o[c];
}

// ---------------- launch ----------------------------------------------------
extern "C" void kernel_launch(void* const* d_in, const int* in_sizes, int n_in,
                              void* d_out, int out_size) {
    const float* x     = (const float*)d_in[0];
    const int*   ei    = (const int*)d_in[1];
    const int*   batch = (const int*)d_in[2];
    const float* w1a = (const float*)d_in[3];
    const float* b1a = (const float*)d_in[4];
    const float* w1b = (const float*)d_in[5];
    const float* b1b = (const float*)d_in[6];
    const float* Wa  = (const float*)d_in[7];
    const float* Ba  = (const float*)d_in[8];
    const float* Wb  = (const float*)d_in[9];
    const float* Bb  = (const float*)d_in[10];
    const float* bng = (const float*)d_in[11];
    const float* bnb = (const float*)d_in[12];
    const float* fc1w = (const float*)d_in[13];
    const float* fc1b = (const float*)d_in[14];
    const float* fc2w = (const float*)d_in[15];
    const float* fc2b = (const float*)d_in[16];
    float* out = (float*)d_out;

    const int4* srcs4 = (const int4*)ei;
    const int4* dsts4 = (const int4*)(ei + NE);

    const int GATHER_GRID = (NN * 8 + 255) / 256;   // 3125
    const int POOL_GRID = (NN * 8 + 255) / 256;

    // launches 1-3: CSR build + proj
    combo_kernel<<<CNT_BLKS + PROJ_BLKS, 256>>>((const float4*)x, w1a, dsts4);
    scan_ab_kernel<<<N_SCAN_BLKS, 256>>>();
    fill_kernel<<<CNT_BLKS, 256>>>(srcs4, dsts4);

    // layer 1 (launch 4 = gather -> profiled)
    gather_kernel<<<GATHER_GRID, 256>>>();
    mlp_kernel<true><<<MLP_GRID, 128>>>(nullptr, b1a, w1b, b1b, 0, bng, bnb);

    // layers 2-5
    for (int i = 0; i < 4; i++) {
        gather_kernel<<<GATHER_GRID, 256>>>();
        mlp_kernel<false><<<MLP_GRID, 128>>>(Wa + i * 1024, Ba + i * 32,
                                             Wb + i * 1024, Bb + i * 32,
                                             i + 1, bng, bnb);
    }

    pool_kernel<<<POOL_GRID, 256>>>(batch, bng, bnb);
    head_kernel<<<1, 64>>>(fc1w, fc1b, fc2w, fc2b, out);
}